// round 4
// baseline (speedup 1.0000x reference)
#include <cuda_runtime.h>
#include <math.h>

// Problem constants
#define Bsz 8
#define Ssz 512
#define Dsz 768
#define Hsz 12
#define DHsz 64
#define FFsz 3072
#define MROWS (Bsz*Ssz)   // 4096

// ---------------------------------------------------------------------------
// Scratch (single __device__ global; no allocations anywhere)
// Layout (floats):
//   qn   : MROWS*Dsz
//   kn   : MROWS*Dsz
//   xn   : MROWS*Dsz
//   q    : MROWS*Dsz
//   k    : MROWS*Dsz
//   v    : MROWS*Dsz
//   ctx  : MROWS*Dsz
//   x1   : MROWS*Dsz
//   xn2  : MROWS*Dsz
//   hid  : MROWS*FFsz
//   L    : Bsz*Ssz
#define SCRATCH_FLOATS (9*(size_t)MROWS*Dsz + (size_t)MROWS*FFsz + Bsz*Ssz)
static __device__ float g_scratch[SCRATCH_FLOATS];
static __device__ unsigned char g_mask[Bsz*Ssz];
static __device__ int g_mask_is_int;

// ---------------------------------------------------------------------------
// Generic tiled GEMM: Y[M,N] = X[M,K] @ W[K,N] + bias (+relu | +residual)
// 64x64 tile, K-tile 16, 256 threads, 4x4 micro-tile, float4 smem reads.
__global__ __launch_bounds__(256) void gemm_bias_kernel(
    const float* __restrict__ X, const float* __restrict__ W,
    const float* __restrict__ bias, const float* __restrict__ res,
    float* __restrict__ Y, int M, int N, int K, int fuse)
{
    __shared__ float As[16][68];
    __shared__ float Bs[16][68];
    const int tid = threadIdx.x;
    const int tx = tid & 15, ty = tid >> 4;
    const int m0 = blockIdx.y << 6, n0 = blockIdx.x << 6;

    const int la_row = tid >> 2;          // 0..63
    const int la_k4  = (tid & 3) << 2;    // 0,4,8,12
    const int lb_k   = tid >> 4;          // 0..15
    const int lb_n4  = (tid & 15) << 2;   // 0..60

    const float* Xp = X + (size_t)(m0 + la_row) * K + la_k4;
    const float* Wp = W + (size_t)lb_k * N + n0 + lb_n4;

    float acc[4][4] = {};
    for (int k0 = 0; k0 < K; k0 += 16) {
        float4 av = *(const float4*)(Xp + k0);
        As[la_k4+0][la_row] = av.x; As[la_k4+1][la_row] = av.y;
        As[la_k4+2][la_row] = av.z; As[la_k4+3][la_row] = av.w;
        float4 bv = *(const float4*)(Wp + (size_t)k0 * N);
        *(float4*)&Bs[lb_k][lb_n4] = bv;
        __syncthreads();
        #pragma unroll
        for (int kk = 0; kk < 16; kk++) {
            float4 a = *(const float4*)&As[kk][ty << 2];
            float4 b = *(const float4*)&Bs[kk][tx << 2];
            acc[0][0] += a.x*b.x; acc[0][1] += a.x*b.y; acc[0][2] += a.x*b.z; acc[0][3] += a.x*b.w;
            acc[1][0] += a.y*b.x; acc[1][1] += a.y*b.y; acc[1][2] += a.y*b.z; acc[1][3] += a.y*b.w;
            acc[2][0] += a.z*b.x; acc[2][1] += a.z*b.y; acc[2][2] += a.z*b.z; acc[2][3] += a.z*b.w;
            acc[3][0] += a.w*b.x; acc[3][1] += a.w*b.y; acc[3][2] += a.w*b.z; acc[3][3] += a.w*b.w;
        }
        __syncthreads();
    }
    #pragma unroll
    for (int i = 0; i < 4; i++) {
        int m = m0 + (ty << 2) + i;
        #pragma unroll
        for (int j = 0; j < 4; j++) {
            int n = n0 + (tx << 2) + j;
            float vv = acc[i][j] + bias[n];
            if (fuse == 1) vv = fmaxf(vv, 0.0f);
            else if (fuse == 2) vv += res[(size_t)m * N + n];
            Y[(size_t)m * N + n] = vv;
        }
    }
}

// ---------------------------------------------------------------------------
// LayerNorm over last dim (768), one block per row.
__global__ __launch_bounds__(256) void layernorm_kernel(
    const float* __restrict__ X, const float* __restrict__ g,
    const float* __restrict__ be, float* __restrict__ Y)
{
    __shared__ float red[256];
    __shared__ float s_mean, s_inv;
    const int row = blockIdx.x, tid = threadIdx.x;
    const float* x = X + (size_t)row * Dsz;

    float s = 0.0f;
    for (int i = tid; i < Dsz; i += 256) s += x[i];
    red[tid] = s; __syncthreads();
    for (int o = 128; o > 0; o >>= 1) { if (tid < o) red[tid] += red[tid + o]; __syncthreads(); }
    if (tid == 0) s_mean = red[0] * (1.0f / Dsz);
    __syncthreads();
    const float m = s_mean;

    float v = 0.0f;
    for (int i = tid; i < Dsz; i += 256) { float d = x[i] - m; v += d * d; }
    red[tid] = v; __syncthreads();
    for (int o = 128; o > 0; o >>= 1) { if (tid < o) red[tid] += red[tid + o]; __syncthreads(); }
    if (tid == 0) s_inv = rsqrtf(red[0] * (1.0f / Dsz) + 1e-5f);
    __syncthreads();
    const float inv = s_inv;

    float* y = Y + (size_t)row * Dsz;
    for (int i = tid; i < Dsz; i += 256) y[i] = (x[i] - m) * inv * g[i] + be[i];
}

// ---------------------------------------------------------------------------
// Neighbor affinity: a[b,t] from dot(qn[b,t],kn[b,t+1]) and dot(qn[b,t+1],kn[b,t])
__global__ __launch_bounds__(128) void affinity_kernel(
    const float* __restrict__ qn, const float* __restrict__ kn,
    const float* __restrict__ prev, const int* __restrict__ lidx,
    float* __restrict__ a_out)
{
    const int t = blockIdx.x, b = blockIdx.y, tid = threadIdx.x;
    const float* q0 = qn + ((size_t)b * Ssz + t) * Dsz;
    const float* q1 = q0 + Dsz;
    const float* k0 = kn + ((size_t)b * Ssz + t) * Dsz;
    const float* k1 = k0 + Dsz;
    float sf = 0.0f, sb = 0.0f;
    for (int i = tid; i < Dsz; i += 128) { sf += q0[i] * k1[i]; sb += q1[i] * k0[i]; }
    __shared__ float rf[128], rb[128];
    rf[tid] = sf; rb[tid] = sb; __syncthreads();
    for (int o = 64; o > 0; o >>= 1) {
        if (tid < o) { rf[tid] += rf[tid + o]; rb[tid] += rb[tid + o]; }
        __syncthreads();
    }
    if (tid == 0) {
        float f = rf[0] * (1.0f / 64.0f), bw = rb[0] * (1.0f / 64.0f);
        float ah = 0.5f * (1.0f / (1.0f + expf(-f)) + 1.0f / (1.0f + expf(-bw)));
        float a;
        if (*lidx == 0) a = ah;
        else { float p = prev[(size_t)b * (Ssz - 1) + t]; a = p + (1.0f - p) * ah; }
        a_out[(size_t)b * (Ssz - 1) + t] = a;
    }
}

// L[b,0]=0; L[b,k]=sum_{t<k} log(a[b,t])  (sequential scan, trivial size)
__global__ void scan_kernel(const float* __restrict__ a, float* __restrict__ Lout)
{
    const int b = blockIdx.x;
    if (threadIdx.x == 0) {
        float acc = 0.0f;
        Lout[(size_t)b * Ssz] = 0.0f;
        for (int t = 0; t < Ssz - 1; t++) {
            acc += logf(a[(size_t)b * (Ssz - 1) + t]);
            Lout[(size_t)b * Ssz + t + 1] = acc;
        }
    }
}

// ---------------------------------------------------------------------------
// Mask dtype handling (jax bool may land as uint8 or int32)
__global__ void mask_detect_kernel(const unsigned char* __restrict__ m)
{
    if (threadIdx.x == 0)
        g_mask_is_int = (m[1] == 0 && m[2] == 0 && m[3] == 0) ? 1 : 0;
}
__global__ void mask_norm_kernel(const void* __restrict__ m)
{
    int i = blockIdx.x * 256 + threadIdx.x;
    if (i < Bsz * Ssz) {
        int v = g_mask_is_int ? ((const int*)m)[i] : (int)((const unsigned char*)m)[i];
        g_mask[i] = v ? 1 : 0;
    }
}

// ---------------------------------------------------------------------------
// Fused attention: per (b,h,32-q-tile): scores -> mask -> softmax -> *C
//  -> write attn_h -> ctx = attn_h @ V.  Dynamic smem 110208 B.
// smem layout (floats): Sc[32][516] | qs[32][65] | kt[128][65] | Ls[512] | ms[512B]
#define ATT_SC 0
#define ATT_QS 16512
#define ATT_KT 18592
#define ATT_LS 26912
#define ATT_MS 27424
#define ATT_SMEM_BYTES ((ATT_MS + 128) * 4)

__global__ __launch_bounds__(256) void attn_fused_kernel(
    const float* __restrict__ gq, const float* __restrict__ gk,
    const float* __restrict__ gv, const float* __restrict__ Lg,
    float* __restrict__ attnh, float* __restrict__ ctx)
{
    extern __shared__ float sm[];
    float* Sc = sm + ATT_SC;                  // 32 x 516
    float* qs = sm + ATT_QS;                  // 32 x 65
    float* kt = sm + ATT_KT;                  // 128 x 65 (K then reused for V)
    float* Ls = sm + ATT_LS;                  // 512
    unsigned char* ms = (unsigned char*)(sm + ATT_MS);  // 512

    const int tid = threadIdx.x;
    const int bh = blockIdx.y, b = bh / Hsz, h = bh % Hsz;
    const int q0 = blockIdx.x * 32;

    for (int i = tid; i < Ssz; i += 256) {
        Ls[i] = Lg[(size_t)b * Ssz + i];
        ms[i] = g_mask[(size_t)b * Ssz + i];
    }
    // load Q tile 32x64
    {
        int r = tid >> 3, d8 = (tid & 7) << 3;
        const float* src = gq + ((size_t)b * Ssz + q0 + r) * Dsz + h * DHsz + d8;
        float* dst = qs + r * 65 + d8;
        #pragma unroll
        for (int u = 0; u < 8; u++) dst[u] = src[u];
    }
    __syncthreads();

    const int qg = tid >> 5;   // 0..7  (4 q rows each)
    const int kg = tid & 31;   // 0..31 (4 strided k cols each)

    // ---- phase 1: scores tile 32x512 (k-tiles of 128) ----
    for (int t = 0; t < 4; t++) {
        const int k0 = t * 128;
        {
            int krow = tid >> 1, dd = (tid & 1) << 5;
            const float* src = gk + ((size_t)b * Ssz + k0 + krow) * Dsz + h * DHsz + dd;
            float* dst = kt + krow * 65 + dd;
            #pragma unroll
            for (int u = 0; u < 32; u++) dst[u] = src[u];
        }
        __syncthreads();
        float acc[4][4] = {};
        #pragma unroll 4
        for (int dh = 0; dh < DHsz; dh++) {
            float qv[4], kv[4];
            #pragma unroll
            for (int i = 0; i < 4; i++) qv[i] = qs[(qg * 4 + i) * 65 + dh];
            #pragma unroll
            for (int j = 0; j < 4; j++) kv[j] = kt[(kg + 32 * j) * 65 + dh];
            #pragma unroll
            for (int i = 0; i < 4; i++)
                #pragma unroll
                for (int j = 0; j < 4; j++) acc[i][j] += qv[i] * kv[j];
        }
        #pragma unroll
        for (int i = 0; i < 4; i++)
            #pragma unroll
            for (int j = 0; j < 4; j++) {
                int kgl = k0 + kg + 32 * j;
                float vv = acc[i][j] * 0.125f;   // 1/sqrt(64)
                if (!ms[kgl]) vv = -1e9f;
                Sc[(qg * 4 + i) * 516 + kgl] = vv;
            }
        __syncthreads();
    }

    // ---- phase 2: softmax + hierarchical C scale ----
    {
        const int row = tid >> 3, l8 = tid & 7;
        float* sr = Sc + row * 516;
        float mx = -1e30f;
        #pragma unroll 8
        for (int i = 0; i < 64; i++) mx = fmaxf(mx, sr[l8 + 8 * i]);
        for (int o = 1; o < 8; o <<= 1) mx = fmaxf(mx, __shfl_xor_sync(0xffffffffu, mx, o));
        float sum = 0.0f;
        #pragma unroll 8
        for (int i = 0; i < 64; i++) {
            int k = l8 + 8 * i;
            float e = expf(sr[k] - mx);
            sr[k] = e; sum += e;
        }
        for (int o = 1; o < 8; o <<= 1) sum += __shfl_xor_sync(0xffffffffu, sum, o);
        const float inv = 1.0f / sum;
        const int qi = q0 + row;
        const float Lq = Ls[qi];
        #pragma unroll 8
        for (int i = 0; i < 64; i++) {
            int k = l8 + 8 * i;
            float Lk = Ls[k];
            float c = (qi >= k) ? expf(Lq - Lk) : expf(Lk - Lq);
            sr[k] = sr[k] * inv * c;
        }
    }
    __syncthreads();

    // ---- write attn_h tile (coalesced) ----
    {
        float* dst = attnh + (size_t)bh * Ssz * Ssz + (size_t)q0 * Ssz;
        for (int idx = tid; idx < 32 * 512; idx += 256) {
            int r = idx >> 9, k = idx & 511;
            dst[(size_t)r * Ssz + k] = Sc[r * 516 + k];
        }
    }

    // ---- phase 3: ctx = attn_h_tile(32x512) @ V(512x64) ----
    float oacc[2][4] = {};
    const int r0 = (tid >> 4) << 1;
    const int c0 = (tid & 15) << 2;
    for (int t = 0; t < 4; t++) {
        const int k0 = t * 128;
        __syncthreads();
        {
            int krow = tid >> 1, dd = (tid & 1) << 5;
            const float* src = gv + ((size_t)b * Ssz + k0 + krow) * Dsz + h * DHsz + dd;
            float* dst = kt + krow * 65 + dd;
            #pragma unroll
            for (int u = 0; u < 32; u++) dst[u] = src[u];
        }
        __syncthreads();
        #pragma unroll 4
        for (int kk = 0; kk < 128; kk++) {
            float a0 = Sc[r0 * 516 + k0 + kk];
            float a1 = Sc[(r0 + 1) * 516 + k0 + kk];
            const float* vr = kt + kk * 65 + c0;
            #pragma unroll
            for (int j = 0; j < 4; j++) { float bv = vr[j]; oacc[0][j] += a0 * bv; oacc[1][j] += a1 * bv; }
        }
    }
    #pragma unroll
    for (int rr = 0; rr < 2; rr++) {
        float4 o4 = make_float4(oacc[rr][0], oacc[rr][1], oacc[rr][2], oacc[rr][3]);
        *(float4*)(ctx + ((size_t)b * Ssz + q0 + r0 + rr) * Dsz + h * DHsz + c0) = o4;
    }
}

// ---------------------------------------------------------------------------
extern "C" void kernel_launch(void* const* d_in, const int* in_sizes, int n_in,
                              void* d_out, int out_size)
{
    (void)in_sizes; (void)n_in; (void)out_size;
    const float* x    = (const float*)d_in[0];
    const void*  mask = d_in[1];
    const float* prev = (const float*)d_in[2];
    const float* Wqn  = (const float*)d_in[3];  const float* bqn = (const float*)d_in[4];
    const float* Wkn  = (const float*)d_in[5];  const float* bkn = (const float*)d_in[6];
    const float* Wq   = (const float*)d_in[7];  const float* bq  = (const float*)d_in[8];
    const float* Wk   = (const float*)d_in[9];  const float* bk  = (const float*)d_in[10];
    const float* Wv   = (const float*)d_in[11]; const float* bv  = (const float*)d_in[12];
    const float* Wo   = (const float*)d_in[13]; const float* bo  = (const float*)d_in[14];
    const float* W1   = (const float*)d_in[15]; const float* b1  = (const float*)d_in[16];
    const float* W2   = (const float*)d_in[17]; const float* b2  = (const float*)d_in[18];
    const float* g1   = (const float*)d_in[19]; const float* be1 = (const float*)d_in[20];
    const float* g2   = (const float*)d_in[21]; const float* be2 = (const float*)d_in[22];
    const int*   lidx = (const int*)d_in[23];

    float* out_p   = (float*)d_out;
    float* a_p     = out_p + (size_t)MROWS * Dsz;
    float* attnh_p = a_p + (size_t)Bsz * (Ssz - 1);

    void* base = nullptr;
    cudaGetSymbolAddress(&base, g_scratch);
    float* qn  = (float*)base;
    float* kn  = qn  + (size_t)MROWS * Dsz;
    float* xn  = kn  + (size_t)MROWS * Dsz;
    float* qb  = xn  + (size_t)MROWS * Dsz;
    float* kb  = qb  + (size_t)MROWS * Dsz;
    float* vb  = kb  + (size_t)MROWS * Dsz;
    float* ctx = vb  + (size_t)MROWS * Dsz;
    float* x1  = ctx + (size_t)MROWS * Dsz;
    float* xn2 = x1  + (size_t)MROWS * Dsz;
    float* hid = xn2 + (size_t)MROWS * Dsz;
    float* Lb  = hid + (size_t)MROWS * FFsz;

    cudaFuncSetAttribute(attn_fused_kernel,
                         cudaFuncAttributeMaxDynamicSharedMemorySize, ATT_SMEM_BYTES);

    const dim3 gD(Dsz / 64, MROWS / 64);   // N=768
    const dim3 gF(FFsz / 64, MROWS / 64);  // N=3072

    // affinity path (uses raw x)
    gemm_bias_kernel<<<gD, 256>>>(x, Wqn, bqn, nullptr, qn, MROWS, Dsz, Dsz, 0);
    gemm_bias_kernel<<<gD, 256>>>(x, Wkn, bkn, nullptr, kn, MROWS, Dsz, Dsz, 0);
    mask_detect_kernel<<<1, 32>>>((const unsigned char*)mask);
    mask_norm_kernel<<<16, 256>>>(mask);
    affinity_kernel<<<dim3(Ssz - 1, Bsz), 128>>>(qn, kn, prev, lidx, a_p);
    scan_kernel<<<Bsz, 32>>>(a_p, Lb);

    // attention path
    layernorm_kernel<<<MROWS, 256>>>(x, g1, be1, xn);
    gemm_bias_kernel<<<gD, 256>>>(xn, Wq, bq, nullptr, qb, MROWS, Dsz, Dsz, 0);
    gemm_bias_kernel<<<gD, 256>>>(xn, Wk, bk, nullptr, kb, MROWS, Dsz, Dsz, 0);
    gemm_bias_kernel<<<gD, 256>>>(xn, Wv, bv, nullptr, vb, MROWS, Dsz, Dsz, 0);
    attn_fused_kernel<<<dim3(Ssz / 32, Bsz * Hsz), 256, ATT_SMEM_BYTES>>>(
        qb, kb, vb, Lb, attnh_p, ctx);

    // output proj + residual, LN2, FFN
    gemm_bias_kernel<<<gD, 256>>>(ctx, Wo, bo, x, x1, MROWS, Dsz, Dsz, 2);
    layernorm_kernel<<<MROWS, 256>>>(x1, g2, be2, xn2);
    gemm_bias_kernel<<<gF, 256>>>(xn2, W1, b1, nullptr, hid, MROWS, FFsz, Dsz, 1);
    gemm_bias_kernel<<<gD, 256>>>(hid, W2, b2, x1, out_p, MROWS, Dsz, FFsz, 2);
}

// round 6
// speedup vs baseline: 1.6535x; 1.6535x over previous
#include <cuda_runtime.h>
#include <math.h>
#include <stdint.h>

// Problem constants
#define Bsz 8
#define Ssz 512
#define Dsz 768
#define Hsz 12
#define DHsz 64
#define FFsz 3072
#define MROWS (Bsz*Ssz)   // 4096

// ---------------------------------------------------------------------------
// Scratch (single __device__ global; no allocations anywhere)
#define SCRATCH_FLOATS (9*(size_t)MROWS*Dsz + (size_t)MROWS*FFsz + Bsz*Ssz)
static __device__ float g_scratch[SCRATCH_FLOATS];
static __device__ unsigned char g_mask[Bsz*Ssz];
static __device__ int g_mask_is_int;

// ---------------------------------------------------------------------------
__device__ __forceinline__ float to_tf32(float x) {
    uint32_t u;
    asm("cvt.rna.tf32.f32 %0, %1;" : "=r"(u) : "f"(x));
    return __uint_as_float(u);
}

__device__ __forceinline__ void mma_tf32(float* c, const float* a, const float* b) {
    asm volatile(
        "mma.sync.aligned.m16n8k8.row.col.f32.tf32.tf32.f32 "
        "{%0,%1,%2,%3}, {%4,%5,%6,%7}, {%8,%9}, {%0,%1,%2,%3};\n"
        : "+f"(c[0]), "+f"(c[1]), "+f"(c[2]), "+f"(c[3])
        : "r"(__float_as_uint(a[0])), "r"(__float_as_uint(a[1])),
          "r"(__float_as_uint(a[2])), "r"(__float_as_uint(a[3])),
          "r"(__float_as_uint(b[0])), "r"(__float_as_uint(b[1])));
}

// ---------------------------------------------------------------------------
// TF32 tensor-core GEMM: Y[M,N] = X[M,K] @ W[K,N] + bias (+relu | +residual)
// CTA tile 128x128, k-tile 16, 256 threads (8 warps), warp tile 64x32.
// Double-buffered smem, conflict-free padded layouts.
#define BM 128
#define BN 128
#define BK 16

__global__ __launch_bounds__(256) void gemm_tf32_kernel(
    const float* __restrict__ X, const float* __restrict__ W,
    const float* __restrict__ bias, const float* __restrict__ res,
    float* __restrict__ Y, int M, int N, int K, int fuse)
{
    __shared__ float As[2][BM][20];    // [buf][m][k], pad 20 -> frag loads conflict-free
    __shared__ float Bs[2][BK][136];   // [buf][k][n], pad 136 -> frag loads conflict-free

    const int tid  = threadIdx.x;
    const int wid  = tid >> 5, lane = tid & 31;
    const int gID  = lane >> 2;        // 0..7
    const int tig  = lane & 3;         // 0..3
    const int warp_m = (wid & 1) * 64;
    const int warp_n = (wid >> 1) * 32;
    const int m0 = blockIdx.y * BM, n0 = blockIdx.x * BN;

    // gmem staging indices
    const int a_row = tid >> 1;            // 0..127
    const int a_col = (tid & 1) * 8;       // 0 or 8
    const int b_row = tid >> 4;            // 0..15
    const int b_col = (tid & 15) * 8;      // 0..120
    const float* Xp = X + (size_t)(m0 + a_row) * K + a_col;
    const float* Wp = W + (size_t)b_row * N + n0 + b_col;

    float acc[4][4][4];
    #pragma unroll
    for (int i = 0; i < 4; i++)
        #pragma unroll
        for (int j = 0; j < 4; j++)
            #pragma unroll
            for (int c = 0; c < 4; c++) acc[i][j][c] = 0.0f;

    const int nk = K / BK;
    float4 pa0, pa1, pb0, pb1;

    // prefetch tile 0
    pa0 = *(const float4*)(Xp);
    pa1 = *(const float4*)(Xp + 4);
    pb0 = *(const float4*)(Wp);
    pb1 = *(const float4*)(Wp + 4);
    {
        float4 t0 = make_float4(to_tf32(pa0.x), to_tf32(pa0.y), to_tf32(pa0.z), to_tf32(pa0.w));
        float4 t1 = make_float4(to_tf32(pa1.x), to_tf32(pa1.y), to_tf32(pa1.z), to_tf32(pa1.w));
        *(float4*)&As[0][a_row][a_col]     = t0;
        *(float4*)&As[0][a_row][a_col + 4] = t1;
        float4 u0 = make_float4(to_tf32(pb0.x), to_tf32(pb0.y), to_tf32(pb0.z), to_tf32(pb0.w));
        float4 u1 = make_float4(to_tf32(pb1.x), to_tf32(pb1.y), to_tf32(pb1.z), to_tf32(pb1.w));
        *(float4*)&Bs[0][b_row][b_col]     = u0;
        *(float4*)&Bs[0][b_row][b_col + 4] = u1;
    }
    __syncthreads();

    for (int kt = 0; kt < nk; kt++) {
        const int buf = kt & 1;
        const bool pf = (kt + 1) < nk;
        if (pf) {
            const float* xp = Xp + (kt + 1) * BK;
            pa0 = *(const float4*)(xp);
            pa1 = *(const float4*)(xp + 4);
            const float* wp = Wp + (size_t)(kt + 1) * BK * N;
            pb0 = *(const float4*)(wp);
            pb1 = *(const float4*)(wp + 4);
        }

        #pragma unroll
        for (int kk = 0; kk < BK; kk += 8) {
            float af[4][4], bf[4][2];
            #pragma unroll
            for (int mt = 0; mt < 4; mt++) {
                const int r = warp_m + mt * 16;
                af[mt][0] = As[buf][r + gID    ][kk + tig];
                af[mt][1] = As[buf][r + gID + 8][kk + tig];
                af[mt][2] = As[buf][r + gID    ][kk + tig + 4];
                af[mt][3] = As[buf][r + gID + 8][kk + tig + 4];
            }
            #pragma unroll
            for (int nt = 0; nt < 4; nt++) {
                const int n = warp_n + nt * 8 + gID;
                bf[nt][0] = Bs[buf][kk + tig    ][n];
                bf[nt][1] = Bs[buf][kk + tig + 4][n];
            }
            #pragma unroll
            for (int mt = 0; mt < 4; mt++)
                #pragma unroll
                for (int nt = 0; nt < 4; nt++)
                    mma_tf32(acc[mt][nt], af[mt], bf[nt]);
        }

        if (pf) {
            const int nb = buf ^ 1;
            float4 t0 = make_float4(to_tf32(pa0.x), to_tf32(pa0.y), to_tf32(pa0.z), to_tf32(pa0.w));
            float4 t1 = make_float4(to_tf32(pa1.x), to_tf32(pa1.y), to_tf32(pa1.z), to_tf32(pa1.w));
            *(float4*)&As[nb][a_row][a_col]     = t0;
            *(float4*)&As[nb][a_row][a_col + 4] = t1;
            float4 u0 = make_float4(to_tf32(pb0.x), to_tf32(pb0.y), to_tf32(pb0.z), to_tf32(pb0.w));
            float4 u1 = make_float4(to_tf32(pb1.x), to_tf32(pb1.y), to_tf32(pb1.z), to_tf32(pb1.w));
            *(float4*)&Bs[nb][b_row][b_col]     = u0;
            *(float4*)&Bs[nb][b_row][b_col + 4] = u1;
            __syncthreads();
        }
    }

    // epilogue
    #pragma unroll
    for (int mt = 0; mt < 4; mt++) {
        const int m = m0 + warp_m + mt * 16 + gID;
        #pragma unroll
        for (int nt = 0; nt < 4; nt++) {
            const int n = n0 + warp_n + nt * 8 + 2 * tig;
            const float* c = acc[mt][nt];
            const float bv0 = bias[n], bv1 = bias[n + 1];
            float v00 = c[0] + bv0, v01 = c[1] + bv1;
            float v10 = c[2] + bv0, v11 = c[3] + bv1;
            if (fuse == 1) {
                v00 = fmaxf(v00, 0.0f); v01 = fmaxf(v01, 0.0f);
                v10 = fmaxf(v10, 0.0f); v11 = fmaxf(v11, 0.0f);
            } else if (fuse == 2) {
                v00 += res[(size_t)m * N + n];     v01 += res[(size_t)m * N + n + 1];
                v10 += res[(size_t)(m + 8) * N + n]; v11 += res[(size_t)(m + 8) * N + n + 1];
            }
            *(float2*)(Y + (size_t)m * N + n)       = make_float2(v00, v01);
            *(float2*)(Y + (size_t)(m + 8) * N + n) = make_float2(v10, v11);
        }
    }
}

// ---------------------------------------------------------------------------
// LayerNorm over last dim (768), one block per row.
__global__ __launch_bounds__(256) void layernorm_kernel(
    const float* __restrict__ X, const float* __restrict__ g,
    const float* __restrict__ be, float* __restrict__ Y)
{
    __shared__ float red[256];
    __shared__ float s_mean, s_inv;
    const int row = blockIdx.x, tid = threadIdx.x;
    const float* x = X + (size_t)row * Dsz;

    float s = 0.0f;
    for (int i = tid; i < Dsz; i += 256) s += x[i];
    red[tid] = s; __syncthreads();
    for (int o = 128; o > 0; o >>= 1) { if (tid < o) red[tid] += red[tid + o]; __syncthreads(); }
    if (tid == 0) s_mean = red[0] * (1.0f / Dsz);
    __syncthreads();
    const float m = s_mean;

    float v = 0.0f;
    for (int i = tid; i < Dsz; i += 256) { float d = x[i] - m; v += d * d; }
    red[tid] = v; __syncthreads();
    for (int o = 128; o > 0; o >>= 1) { if (tid < o) red[tid] += red[tid + o]; __syncthreads(); }
    if (tid == 0) s_inv = rsqrtf(red[0] * (1.0f / Dsz) + 1e-5f);
    __syncthreads();
    const float inv = s_inv;

    float* y = Y + (size_t)row * Dsz;
    for (int i = tid; i < Dsz; i += 256) y[i] = (x[i] - m) * inv * g[i] + be[i];
}

// ---------------------------------------------------------------------------
// Neighbor affinity
__global__ __launch_bounds__(128) void affinity_kernel(
    const float* __restrict__ qn, const float* __restrict__ kn,
    const float* __restrict__ prev, const int* __restrict__ lidx,
    float* __restrict__ a_out)
{
    const int t = blockIdx.x, b = blockIdx.y, tid = threadIdx.x;
    const float* q0 = qn + ((size_t)b * Ssz + t) * Dsz;
    const float* q1 = q0 + Dsz;
    const float* k0 = kn + ((size_t)b * Ssz + t) * Dsz;
    const float* k1 = k0 + Dsz;
    float sf = 0.0f, sb = 0.0f;
    for (int i = tid; i < Dsz; i += 128) { sf += q0[i] * k1[i]; sb += q1[i] * k0[i]; }
    __shared__ float rf[128], rb[128];
    rf[tid] = sf; rb[tid] = sb; __syncthreads();
    for (int o = 64; o > 0; o >>= 1) {
        if (tid < o) { rf[tid] += rf[tid + o]; rb[tid] += rb[tid + o]; }
        __syncthreads();
    }
    if (tid == 0) {
        float f = rf[0] * (1.0f / 64.0f), bw = rb[0] * (1.0f / 64.0f);
        float ah = 0.5f * (1.0f / (1.0f + expf(-f)) + 1.0f / (1.0f + expf(-bw)));
        float a;
        if (*lidx == 0) a = ah;
        else { float p = prev[(size_t)b * (Ssz - 1) + t]; a = p + (1.0f - p) * ah; }
        a_out[(size_t)b * (Ssz - 1) + t] = a;
    }
}

// L[b,0]=0; L[b,k]=sum_{t<k} log(a[b,t])
__global__ void scan_kernel(const float* __restrict__ a, float* __restrict__ Lout)
{
    const int b = blockIdx.x;
    if (threadIdx.x == 0) {
        float acc = 0.0f;
        Lout[(size_t)b * Ssz] = 0.0f;
        for (int t = 0; t < Ssz - 1; t++) {
            acc += logf(a[(size_t)b * (Ssz - 1) + t]);
            Lout[(size_t)b * Ssz + t + 1] = acc;
        }
    }
}

// ---------------------------------------------------------------------------
// Mask dtype handling (jax bool may land as uint8 or int32)
__global__ void mask_detect_kernel(const unsigned char* __restrict__ m)
{
    if (threadIdx.x == 0)
        g_mask_is_int = (m[1] == 0 && m[2] == 0 && m[3] == 0) ? 1 : 0;
}
__global__ void mask_norm_kernel(const void* __restrict__ m)
{
    int i = blockIdx.x * 256 + threadIdx.x;
    if (i < Bsz * Ssz) {
        int v = g_mask_is_int ? ((const int*)m)[i] : (int)((const unsigned char*)m)[i];
        g_mask[i] = v ? 1 : 0;
    }
}

// ---------------------------------------------------------------------------
// Fused attention (unchanged from R3 passing version)
#define ATT_SC 0
#define ATT_QS 16512
#define ATT_KT 18592
#define ATT_LS 26912
#define ATT_MS 27424
#define ATT_SMEM_BYTES ((ATT_MS + 128) * 4)

__global__ __launch_bounds__(256) void attn_fused_kernel(
    const float* __restrict__ gq, const float* __restrict__ gk,
    const float* __restrict__ gv, const float* __restrict__ Lg,
    float* __restrict__ attnh, float* __restrict__ ctx)
{
    extern __shared__ float sm[];
    float* Sc = sm + ATT_SC;
    float* qs = sm + ATT_QS;
    float* kt = sm + ATT_KT;
    float* Ls = sm + ATT_LS;
    unsigned char* ms = (unsigned char*)(sm + ATT_MS);

    const int tid = threadIdx.x;
    const int bh = blockIdx.y, b = bh / Hsz, h = bh % Hsz;
    const int q0 = blockIdx.x * 32;

    for (int i = tid; i < Ssz; i += 256) {
        Ls[i] = Lg[(size_t)b * Ssz + i];
        ms[i] = g_mask[(size_t)b * Ssz + i];
    }
    {
        int r = tid >> 3, d8 = (tid & 7) << 3;
        const float* src = gq + ((size_t)b * Ssz + q0 + r) * Dsz + h * DHsz + d8;
        float* dst = qs + r * 65 + d8;
        #pragma unroll
        for (int u = 0; u < 8; u++) dst[u] = src[u];
    }
    __syncthreads();

    const int qg = tid >> 5;
    const int kg = tid & 31;

    for (int t = 0; t < 4; t++) {
        const int k0 = t * 128;
        {
            int krow = tid >> 1, dd = (tid & 1) << 5;
            const float* src = gk + ((size_t)b * Ssz + k0 + krow) * Dsz + h * DHsz + dd;
            float* dst = kt + krow * 65 + dd;
            #pragma unroll
            for (int u = 0; u < 32; u++) dst[u] = src[u];
        }
        __syncthreads();
        float acc[4][4] = {};
        #pragma unroll 4
        for (int dh = 0; dh < DHsz; dh++) {
            float qv[4], kv[4];
            #pragma unroll
            for (int i = 0; i < 4; i++) qv[i] = qs[(qg * 4 + i) * 65 + dh];
            #pragma unroll
            for (int j = 0; j < 4; j++) kv[j] = kt[(kg + 32 * j) * 65 + dh];
            #pragma unroll
            for (int i = 0; i < 4; i++)
                #pragma unroll
                for (int j = 0; j < 4; j++) acc[i][j] += qv[i] * kv[j];
        }
        #pragma unroll
        for (int i = 0; i < 4; i++)
            #pragma unroll
            for (int j = 0; j < 4; j++) {
                int kgl = k0 + kg + 32 * j;
                float vv = acc[i][j] * 0.125f;
                if (!ms[kgl]) vv = -1e9f;
                Sc[(qg * 4 + i) * 516 + kgl] = vv;
            }
        __syncthreads();
    }

    {
        const int row = tid >> 3, l8 = tid & 7;
        float* sr = Sc + row * 516;
        float mx = -1e30f;
        #pragma unroll 8
        for (int i = 0; i < 64; i++) mx = fmaxf(mx, sr[l8 + 8 * i]);
        for (int o = 1; o < 8; o <<= 1) mx = fmaxf(mx, __shfl_xor_sync(0xffffffffu, mx, o));
        float sum = 0.0f;
        #pragma unroll 8
        for (int i = 0; i < 64; i++) {
            int k = l8 + 8 * i;
            float e = expf(sr[k] - mx);
            sr[k] = e; sum += e;
        }
        for (int o = 1; o < 8; o <<= 1) sum += __shfl_xor_sync(0xffffffffu, sum, o);
        const float inv = 1.0f / sum;
        const int qi = q0 + row;
        const float Lq = Ls[qi];
        #pragma unroll 8
        for (int i = 0; i < 64; i++) {
            int k = l8 + 8 * i;
            float Lk = Ls[k];
            float c = (qi >= k) ? expf(Lq - Lk) : expf(Lk - Lq);
            sr[k] = sr[k] * inv * c;
        }
    }
    __syncthreads();

    {
        float* dst = attnh + (size_t)bh * Ssz * Ssz + (size_t)q0 * Ssz;
        for (int idx = tid; idx < 32 * 512; idx += 256) {
            int r = idx >> 9, k = idx & 511;
            dst[(size_t)r * Ssz + k] = Sc[r * 516 + k];
        }
    }

    float oacc[2][4] = {};
    const int r0 = (tid >> 4) << 1;
    const int c0 = (tid & 15) << 2;
    for (int t = 0; t < 4; t++) {
        const int k0 = t * 128;
        __syncthreads();
        {
            int krow = tid >> 1, dd = (tid & 1) << 5;
            const float* src = gv + ((size_t)b * Ssz + k0 + krow) * Dsz + h * DHsz + dd;
            float* dst = kt + krow * 65 + dd;
            #pragma unroll
            for (int u = 0; u < 32; u++) dst[u] = src[u];
        }
        __syncthreads();
        #pragma unroll 4
        for (int kk = 0; kk < 128; kk++) {
            float a0 = Sc[r0 * 516 + k0 + kk];
            float a1 = Sc[(r0 + 1) * 516 + k0 + kk];
            const float* vr = kt + kk * 65 + c0;
            #pragma unroll
            for (int j = 0; j < 4; j++) { float bv = vr[j]; oacc[0][j] += a0 * bv; oacc[1][j] += a1 * bv; }
        }
    }
    #pragma unroll
    for (int rr = 0; rr < 2; rr++) {
        float4 o4 = make_float4(oacc[rr][0], oacc[rr][1], oacc[rr][2], oacc[rr][3]);
        *(float4*)(ctx + ((size_t)b * Ssz + q0 + r0 + rr) * Dsz + h * DHsz + c0) = o4;
    }
}

// ---------------------------------------------------------------------------
extern "C" void kernel_launch(void* const* d_in, const int* in_sizes, int n_in,
                              void* d_out, int out_size)
{
    (void)in_sizes; (void)n_in; (void)out_size;
    const float* x    = (const float*)d_in[0];
    const void*  mask = d_in[1];
    const float* prev = (const float*)d_in[2];
    const float* Wqn  = (const float*)d_in[3];  const float* bqn = (const float*)d_in[4];
    const float* Wkn  = (const float*)d_in[5];  const float* bkn = (const float*)d_in[6];
    const float* Wq   = (const float*)d_in[7];  const float* bq  = (const float*)d_in[8];
    const float* Wk   = (const float*)d_in[9];  const float* bk  = (const float*)d_in[10];
    const float* Wv   = (const float*)d_in[11]; const float* bv  = (const float*)d_in[12];
    const float* Wo   = (const float*)d_in[13]; const float* bo  = (const float*)d_in[14];
    const float* W1   = (const float*)d_in[15]; const float* b1  = (const float*)d_in[16];
    const float* W2   = (const float*)d_in[17]; const float* b2  = (const float*)d_in[18];
    const float* g1   = (const float*)d_in[19]; const float* be1 = (const float*)d_in[20];
    const float* g2   = (const float*)d_in[21]; const float* be2 = (const float*)d_in[22];
    const int*   lidx = (const int*)d_in[23];

    float* out_p   = (float*)d_out;
    float* a_p     = out_p + (size_t)MROWS * Dsz;
    float* attnh_p = a_p + (size_t)Bsz * (Ssz - 1);

    void* base = nullptr;
    cudaGetSymbolAddress(&base, g_scratch);
    float* qn  = (float*)base;
    float* kn  = qn  + (size_t)MROWS * Dsz;
    float* xn  = kn  + (size_t)MROWS * Dsz;
    float* qb  = xn  + (size_t)MROWS * Dsz;
    float* kb  = qb  + (size_t)MROWS * Dsz;
    float* vb  = kb  + (size_t)MROWS * Dsz;
    float* ctx = vb  + (size_t)MROWS * Dsz;
    float* x1  = ctx + (size_t)MROWS * Dsz;
    float* xn2 = x1  + (size_t)MROWS * Dsz;
    float* hid = xn2 + (size_t)MROWS * Dsz;
    float* Lb  = hid + (size_t)MROWS * FFsz;

    cudaFuncSetAttribute(attn_fused_kernel,
                         cudaFuncAttributeMaxDynamicSharedMemorySize, ATT_SMEM_BYTES);

    const dim3 gD(Dsz / BN, MROWS / BM);    // 6 x 32
    const dim3 gF(FFsz / BN, MROWS / BM);   // 24 x 32

    // affinity path (uses raw x)
    gemm_tf32_kernel<<<gD, 256>>>(x, Wqn, bqn, nullptr, qn, MROWS, Dsz, Dsz, 0);
    gemm_tf32_kernel<<<gD, 256>>>(x, Wkn, bkn, nullptr, kn, MROWS, Dsz, Dsz, 0);
    mask_detect_kernel<<<1, 32>>>((const unsigned char*)mask);
    mask_norm_kernel<<<16, 256>>>(mask);
    affinity_kernel<<<dim3(Ssz - 1, Bsz), 128>>>(qn, kn, prev, lidx, a_p);
    scan_kernel<<<Bsz, 32>>>(a_p, Lb);

    // attention path
    layernorm_kernel<<<MROWS, 256>>>(x, g1, be1, xn);
    gemm_tf32_kernel<<<gD, 256>>>(xn, Wq, bq, nullptr, qb, MROWS, Dsz, Dsz, 0);
    gemm_tf32_kernel<<<gD, 256>>>(xn, Wk, bk, nullptr, kb, MROWS, Dsz, Dsz, 0);
    gemm_tf32_kernel<<<gD, 256>>>(xn, Wv, bv, nullptr, vb, MROWS, Dsz, Dsz, 0);
    attn_fused_kernel<<<dim3(Ssz / 32, Bsz * Hsz), 256, ATT_SMEM_BYTES>>>(
        qb, kb, vb, Lb, attnh_p, ctx);

    // output proj + residual, LN2, FFN
    gemm_tf32_kernel<<<gD, 256>>>(ctx, Wo, bo, x, x1, MROWS, Dsz, Dsz, 2);
    layernorm_kernel<<<MROWS, 256>>>(x1, g2, be2, xn2);
    gemm_tf32_kernel<<<gF, 256>>>(xn2, W1, b1, nullptr, hid, MROWS, FFsz, Dsz, 1);
    gemm_tf32_kernel<<<gD, 256>>>(hid, W2, b2, x1, out_p, MROWS, Dsz, FFsz, 2);
}

// round 7
// speedup vs baseline: 1.8315x; 1.1077x over previous
#include <cuda_runtime.h>
#include <math.h>
#include <stdint.h>

// Problem constants
#define Bsz 8
#define Ssz 512
#define Dsz 768
#define Hsz 12
#define DHsz 64
#define FFsz 3072
#define MROWS (Bsz*Ssz)   // 4096

// ---------------------------------------------------------------------------
// Scratch (single __device__ global; no allocations anywhere)
#define SCRATCH_FLOATS (9*(size_t)MROWS*Dsz + (size_t)MROWS*FFsz + Bsz*Ssz)
static __device__ float g_scratch[SCRATCH_FLOATS];
static __device__ unsigned char g_mask[Bsz*Ssz];
static __device__ int g_mask_is_int;

// ---------------------------------------------------------------------------
__device__ __forceinline__ float to_tf32(float x) {
    uint32_t u;
    asm("cvt.rna.tf32.f32 %0, %1;" : "=r"(u) : "f"(x));
    return __uint_as_float(u);
}

__device__ __forceinline__ void mma_tf32(float* c, const float* a, const float* b) {
    asm volatile(
        "mma.sync.aligned.m16n8k8.row.col.f32.tf32.tf32.f32 "
        "{%0,%1,%2,%3}, {%4,%5,%6,%7}, {%8,%9}, {%0,%1,%2,%3};\n"
        : "+f"(c[0]), "+f"(c[1]), "+f"(c[2]), "+f"(c[3])
        : "r"(__float_as_uint(a[0])), "r"(__float_as_uint(a[1])),
          "r"(__float_as_uint(a[2])), "r"(__float_as_uint(a[3])),
          "r"(__float_as_uint(b[0])), "r"(__float_as_uint(b[1])));
}

// ---------------------------------------------------------------------------
// TF32 tensor-core GEMM v2: BK=32, fragment-major A layout, batched over z.
// CTA tile 128x128, 256 threads (8 warps), warp tile 64x32.
// Dynamic smem: A frags 2x1024 float4 (32KB) + B 2x32x136 floats (34816B).
#define BM 128
#define BN 128
#define BK 32
#define A_F4_BUF 1024         // float4 per buffer
#define B_FLT_BUF (32*136)    // floats per buffer
#define GEMM_SMEM_BYTES (2*A_F4_BUF*16 + 2*B_FLT_BUF*4)   // 67584

struct GemmArgs { const float* X; const float* W; const float* bias; const float* res; float* Y; };
struct GemmBatch { GemmArgs a[3]; };

__global__ __launch_bounds__(256, 2) void gemm_tf32b_kernel(
    GemmBatch gb, int M, int N, int K, int fuse)
{
    const GemmArgs ga = gb.a[blockIdx.z];
    const float* __restrict__ X = ga.X;
    const float* __restrict__ W = ga.W;
    const float* __restrict__ bias = ga.bias;
    const float* __restrict__ res = ga.res;
    float* __restrict__ Y = ga.Y;

    extern __shared__ float4 dsm4[];
    float4* Af = dsm4;                         // [2][4 kkg][8 mtile][4 t][8 c]
    float*  Bf = (float*)(dsm4 + 2*A_F4_BUF);  // [2][32][136]

    const int tid  = threadIdx.x;
    const int wid  = tid >> 5, lane = tid & 31;
    const int gID  = lane >> 2;        // 0..7
    const int tig  = lane & 3;         // 0..3
    const int warp_n = (wid >> 1) * 32;
    const int m0 = blockIdx.y * BM, n0 = blockIdx.x * BN;

    // staging indices
    const int ar  = tid >> 1;            // A row 0..127
    const int acb = (tid & 1) * 4;       // A col base 0 or 4
    const int br  = tid >> 3;            // B row 0..31
    const int bcb = (tid & 7) * 4;       // B col base 0..28
    const float* Xp = X + (size_t)(m0 + ar) * K + acb;
    const float* Wp = W + (size_t)br * N + n0 + bcb;

    // A scatter constants
    const int a_g = ar & 7, a_hi = (ar >> 3) & 1, a_mtile = ar >> 4, a_kb = tid & 1;
    const int a_slot = a_hi + 2 * a_kb;

    float acc[4][4][4];
    #pragma unroll
    for (int i = 0; i < 4; i++)
        #pragma unroll
        for (int j = 0; j < 4; j++)
            #pragma unroll
            for (int c = 0; c < 4; c++) acc[i][j][c] = 0.0f;

    const int nk = K / BK;
    float4 pa[4], pb[4];

    // ---- prologue: stage tile 0 ----
    #pragma unroll
    for (int u = 0; u < 4; u++) pa[u] = *(const float4*)(Xp + 8 * u);
    #pragma unroll
    for (int j = 0; j < 4; j++) pb[j] = *(const float4*)(Wp + 32 * j);
    {
        float* Abase = (float*)Af;
        #pragma unroll
        for (int u = 0; u < 4; u++) {
            float v[4] = {pa[u].x, pa[u].y, pa[u].z, pa[u].w};
            #pragma unroll
            for (int t = 0; t < 4; t++) {
                int c = (a_g + 2 * t) & 7;
                int f4 = ((u * 8 + a_mtile) * 4 + t) * 8 + c;
                Abase[f4 * 4 + a_slot] = to_tf32(v[t]);
            }
        }
        #pragma unroll
        for (int j = 0; j < 4; j++) {
            float4 t4 = make_float4(to_tf32(pb[j].x), to_tf32(pb[j].y),
                                    to_tf32(pb[j].z), to_tf32(pb[j].w));
            *(float4*)&Bf[br * 136 + bcb + 32 * j] = t4;
        }
    }
    __syncthreads();

    for (int kt = 0; kt < nk; kt++) {
        const int buf = kt & 1;
        const bool pf = (kt + 1) < nk;
        if (pf) {
            const float* xp = Xp + (kt + 1) * BK;
            #pragma unroll
            for (int u = 0; u < 4; u++) pa[u] = *(const float4*)(xp + 8 * u);
            const float* wp = Wp + (size_t)(kt + 1) * BK * N;
            #pragma unroll
            for (int j = 0; j < 4; j++) pb[j] = *(const float4*)(wp + 32 * j);
        }

        const float4* Ab = Af + buf * A_F4_BUF;
        const float*  Bb = Bf + buf * B_FLT_BUF;
        #pragma unroll
        for (int kkg = 0; kkg < 4; kkg++) {
            float4 afv[4];
            float  bfv[4][2];
            #pragma unroll
            for (int mt = 0; mt < 4; mt++) {
                const int mtile = (wid & 1) * 4 + mt;
                afv[mt] = Ab[((kkg * 8 + mtile) * 4 + tig) * 8 + ((gID + 2 * tig) & 7)];
            }
            #pragma unroll
            for (int nt = 0; nt < 4; nt++) {
                const int n = warp_n + nt * 8 + gID;
                bfv[nt][0] = Bb[(kkg * 8 + tig)     * 136 + n];
                bfv[nt][1] = Bb[(kkg * 8 + tig + 4) * 136 + n];
            }
            #pragma unroll
            for (int mt = 0; mt < 4; mt++)
                #pragma unroll
                for (int nt = 0; nt < 4; nt++)
                    mma_tf32(acc[mt][nt], (const float*)&afv[mt], bfv[nt]);
        }

        if (pf) {
            const int nb = buf ^ 1;
            float* Abase = (float*)(Af + nb * A_F4_BUF);
            #pragma unroll
            for (int u = 0; u < 4; u++) {
                float v[4] = {pa[u].x, pa[u].y, pa[u].z, pa[u].w};
                #pragma unroll
                for (int t = 0; t < 4; t++) {
                    int c = (a_g + 2 * t) & 7;
                    int f4 = ((u * 8 + a_mtile) * 4 + t) * 8 + c;
                    Abase[f4 * 4 + a_slot] = to_tf32(v[t]);
                }
            }
            float* Bbase = Bf + nb * B_FLT_BUF;
            #pragma unroll
            for (int j = 0; j < 4; j++) {
                float4 t4 = make_float4(to_tf32(pb[j].x), to_tf32(pb[j].y),
                                        to_tf32(pb[j].z), to_tf32(pb[j].w));
                *(float4*)&Bbase[br * 136 + bcb + 32 * j] = t4;
            }
            __syncthreads();
        }
    }

    // epilogue
    const int warp_m = (wid & 1) * 64;
    #pragma unroll
    for (int mt = 0; mt < 4; mt++) {
        const int m = m0 + warp_m + mt * 16 + gID;
        #pragma unroll
        for (int nt = 0; nt < 4; nt++) {
            const int n = n0 + warp_n + nt * 8 + 2 * tig;
            const float* c = acc[mt][nt];
            const float bv0 = bias[n], bv1 = bias[n + 1];
            float v00 = c[0] + bv0, v01 = c[1] + bv1;
            float v10 = c[2] + bv0, v11 = c[3] + bv1;
            if (fuse == 1) {
                v00 = fmaxf(v00, 0.0f); v01 = fmaxf(v01, 0.0f);
                v10 = fmaxf(v10, 0.0f); v11 = fmaxf(v11, 0.0f);
            } else if (fuse == 2) {
                v00 += res[(size_t)m * N + n];       v01 += res[(size_t)m * N + n + 1];
                v10 += res[(size_t)(m + 8) * N + n]; v11 += res[(size_t)(m + 8) * N + n + 1];
            }
            *(float2*)(Y + (size_t)m * N + n)       = make_float2(v00, v01);
            *(float2*)(Y + (size_t)(m + 8) * N + n) = make_float2(v10, v11);
        }
    }
}

// ---------------------------------------------------------------------------
// LayerNorm over last dim (768), one block per row.
__global__ __launch_bounds__(256) void layernorm_kernel(
    const float* __restrict__ X, const float* __restrict__ g,
    const float* __restrict__ be, float* __restrict__ Y)
{
    __shared__ float red[256];
    __shared__ float s_mean, s_inv;
    const int row = blockIdx.x, tid = threadIdx.x;
    const float* x = X + (size_t)row * Dsz;

    float s = 0.0f;
    for (int i = tid; i < Dsz; i += 256) s += x[i];
    red[tid] = s; __syncthreads();
    for (int o = 128; o > 0; o >>= 1) { if (tid < o) red[tid] += red[tid + o]; __syncthreads(); }
    if (tid == 0) s_mean = red[0] * (1.0f / Dsz);
    __syncthreads();
    const float m = s_mean;

    float v = 0.0f;
    for (int i = tid; i < Dsz; i += 256) { float d = x[i] - m; v += d * d; }
    red[tid] = v; __syncthreads();
    for (int o = 128; o > 0; o >>= 1) { if (tid < o) red[tid] += red[tid + o]; __syncthreads(); }
    if (tid == 0) s_inv = rsqrtf(red[0] * (1.0f / Dsz) + 1e-5f);
    __syncthreads();
    const float inv = s_inv;

    float* y = Y + (size_t)row * Dsz;
    for (int i = tid; i < Dsz; i += 256) y[i] = (x[i] - m) * inv * g[i] + be[i];
}

// ---------------------------------------------------------------------------
// Neighbor affinity
__global__ __launch_bounds__(128) void affinity_kernel(
    const float* __restrict__ qn, const float* __restrict__ kn,
    const float* __restrict__ prev, const int* __restrict__ lidx,
    float* __restrict__ a_out)
{
    const int t = blockIdx.x, b = blockIdx.y, tid = threadIdx.x;
    const float* q0 = qn + ((size_t)b * Ssz + t) * Dsz;
    const float* q1 = q0 + Dsz;
    const float* k0 = kn + ((size_t)b * Ssz + t) * Dsz;
    const float* k1 = k0 + Dsz;
    float sf = 0.0f, sb = 0.0f;
    for (int i = tid; i < Dsz; i += 128) { sf += q0[i] * k1[i]; sb += q1[i] * k0[i]; }
    __shared__ float rf[128], rb[128];
    rf[tid] = sf; rb[tid] = sb; __syncthreads();
    for (int o = 64; o > 0; o >>= 1) {
        if (tid < o) { rf[tid] += rf[tid + o]; rb[tid] += rb[tid + o]; }
        __syncthreads();
    }
    if (tid == 0) {
        float f = rf[0] * (1.0f / 64.0f), bw = rb[0] * (1.0f / 64.0f);
        float ah = 0.5f * (1.0f / (1.0f + expf(-f)) + 1.0f / (1.0f + expf(-bw)));
        float a;
        if (*lidx == 0) a = ah;
        else { float p = prev[(size_t)b * (Ssz - 1) + t]; a = p + (1.0f - p) * ah; }
        a_out[(size_t)b * (Ssz - 1) + t] = a;
    }
}

// L[b,0]=0; L[b,k]=sum_{t<k} log(a[b,t])
__global__ void scan_kernel(const float* __restrict__ a, float* __restrict__ Lout)
{
    const int b = blockIdx.x;
    if (threadIdx.x == 0) {
        float acc = 0.0f;
        Lout[(size_t)b * Ssz] = 0.0f;
        for (int t = 0; t < Ssz - 1; t++) {
            acc += logf(a[(size_t)b * (Ssz - 1) + t]);
            Lout[(size_t)b * Ssz + t + 1] = acc;
        }
    }
}

// ---------------------------------------------------------------------------
// Mask dtype handling (jax bool may land as uint8 or int32)
__global__ void mask_detect_kernel(const unsigned char* __restrict__ m)
{
    if (threadIdx.x == 0)
        g_mask_is_int = (m[1] == 0 && m[2] == 0 && m[3] == 0) ? 1 : 0;
}
__global__ void mask_norm_kernel(const void* __restrict__ m)
{
    int i = blockIdx.x * 256 + threadIdx.x;
    if (i < Bsz * Ssz) {
        int v = g_mask_is_int ? ((const int*)m)[i] : (int)((const unsigned char*)m)[i];
        g_mask[i] = v ? 1 : 0;
    }
}

// ---------------------------------------------------------------------------
// Fused attention (unchanged — passing since R3)
#define ATT_SC 0
#define ATT_QS 16512
#define ATT_KT 18592
#define ATT_LS 26912
#define ATT_MS 27424
#define ATT_SMEM_BYTES ((ATT_MS + 128) * 4)

__global__ __launch_bounds__(256) void attn_fused_kernel(
    const float* __restrict__ gq, const float* __restrict__ gk,
    const float* __restrict__ gv, const float* __restrict__ Lg,
    float* __restrict__ attnh, float* __restrict__ ctx)
{
    extern __shared__ float sm[];
    float* Sc = sm + ATT_SC;
    float* qs = sm + ATT_QS;
    float* kt = sm + ATT_KT;
    float* Ls = sm + ATT_LS;
    unsigned char* ms = (unsigned char*)(sm + ATT_MS);

    const int tid = threadIdx.x;
    const int bh = blockIdx.y, b = bh / Hsz, h = bh % Hsz;
    const int q0 = blockIdx.x * 32;

    for (int i = tid; i < Ssz; i += 256) {
        Ls[i] = Lg[(size_t)b * Ssz + i];
        ms[i] = g_mask[(size_t)b * Ssz + i];
    }
    {
        int r = tid >> 3, d8 = (tid & 7) << 3;
        const float* src = gq + ((size_t)b * Ssz + q0 + r) * Dsz + h * DHsz + d8;
        float* dst = qs + r * 65 + d8;
        #pragma unroll
        for (int u = 0; u < 8; u++) dst[u] = src[u];
    }
    __syncthreads();

    const int qg = tid >> 5;
    const int kg = tid & 31;

    for (int t = 0; t < 4; t++) {
        const int k0 = t * 128;
        {
            int krow = tid >> 1, dd = (tid & 1) << 5;
            const float* src = gk + ((size_t)b * Ssz + k0 + krow) * Dsz + h * DHsz + dd;
            float* dst = kt + krow * 65 + dd;
            #pragma unroll
            for (int u = 0; u < 32; u++) dst[u] = src[u];
        }
        __syncthreads();
        float acc[4][4] = {};
        #pragma unroll 4
        for (int dh = 0; dh < DHsz; dh++) {
            float qv[4], kv[4];
            #pragma unroll
            for (int i = 0; i < 4; i++) qv[i] = qs[(qg * 4 + i) * 65 + dh];
            #pragma unroll
            for (int j = 0; j < 4; j++) kv[j] = kt[(kg + 32 * j) * 65 + dh];
            #pragma unroll
            for (int i = 0; i < 4; i++)
                #pragma unroll
                for (int j = 0; j < 4; j++) acc[i][j] += qv[i] * kv[j];
        }
        #pragma unroll
        for (int i = 0; i < 4; i++)
            #pragma unroll
            for (int j = 0; j < 4; j++) {
                int kgl = k0 + kg + 32 * j;
                float vv = acc[i][j] * 0.125f;
                if (!ms[kgl]) vv = -1e9f;
                Sc[(qg * 4 + i) * 516 + kgl] = vv;
            }
        __syncthreads();
    }

    {
        const int row = tid >> 3, l8 = tid & 7;
        float* sr = Sc + row * 516;
        float mx = -1e30f;
        #pragma unroll 8
        for (int i = 0; i < 64; i++) mx = fmaxf(mx, sr[l8 + 8 * i]);
        for (int o = 1; o < 8; o <<= 1) mx = fmaxf(mx, __shfl_xor_sync(0xffffffffu, mx, o));
        float sum = 0.0f;
        #pragma unroll 8
        for (int i = 0; i < 64; i++) {
            int k = l8 + 8 * i;
            float e = expf(sr[k] - mx);
            sr[k] = e; sum += e;
        }
        for (int o = 1; o < 8; o <<= 1) sum += __shfl_xor_sync(0xffffffffu, sum, o);
        const float inv = 1.0f / sum;
        const int qi = q0 + row;
        const float Lq = Ls[qi];
        #pragma unroll 8
        for (int i = 0; i < 64; i++) {
            int k = l8 + 8 * i;
            float Lk = Ls[k];
            float c = (qi >= k) ? expf(Lq - Lk) : expf(Lk - Lq);
            sr[k] = sr[k] * inv * c;
        }
    }
    __syncthreads();

    {
        float* dst = attnh + (size_t)bh * Ssz * Ssz + (size_t)q0 * Ssz;
        for (int idx = tid; idx < 32 * 512; idx += 256) {
            int r = idx >> 9, k = idx & 511;
            dst[(size_t)r * Ssz + k] = Sc[r * 516 + k];
        }
    }

    float oacc[2][4] = {};
    const int r0 = (tid >> 4) << 1;
    const int c0 = (tid & 15) << 2;
    for (int t = 0; t < 4; t++) {
        const int k0 = t * 128;
        __syncthreads();
        {
            int krow = tid >> 1, dd = (tid & 1) << 5;
            const float* src = gv + ((size_t)b * Ssz + k0 + krow) * Dsz + h * DHsz + dd;
            float* dst = kt + krow * 65 + dd;
            #pragma unroll
            for (int u = 0; u < 32; u++) dst[u] = src[u];
        }
        __syncthreads();
        #pragma unroll 4
        for (int kk = 0; kk < 128; kk++) {
            float a0 = Sc[r0 * 516 + k0 + kk];
            float a1 = Sc[(r0 + 1) * 516 + k0 + kk];
            const float* vr = kt + kk * 65 + c0;
            #pragma unroll
            for (int j = 0; j < 4; j++) { float bv = vr[j]; oacc[0][j] += a0 * bv; oacc[1][j] += a1 * bv; }
        }
    }
    #pragma unroll
    for (int rr = 0; rr < 2; rr++) {
        float4 o4 = make_float4(oacc[rr][0], oacc[rr][1], oacc[rr][2], oacc[rr][3]);
        *(float4*)(ctx + ((size_t)b * Ssz + q0 + r0 + rr) * Dsz + h * DHsz + c0) = o4;
    }
}

// ---------------------------------------------------------------------------
extern "C" void kernel_launch(void* const* d_in, const int* in_sizes, int n_in,
                              void* d_out, int out_size)
{
    (void)in_sizes; (void)n_in; (void)out_size;
    const float* x    = (const float*)d_in[0];
    const void*  mask = d_in[1];
    const float* prev = (const float*)d_in[2];
    const float* Wqn  = (const float*)d_in[3];  const float* bqn = (const float*)d_in[4];
    const float* Wkn  = (const float*)d_in[5];  const float* bkn = (const float*)d_in[6];
    const float* Wq   = (const float*)d_in[7];  const float* bq  = (const float*)d_in[8];
    const float* Wk   = (const float*)d_in[9];  const float* bk  = (const float*)d_in[10];
    const float* Wv   = (const float*)d_in[11]; const float* bv  = (const float*)d_in[12];
    const float* Wo   = (const float*)d_in[13]; const float* bo  = (const float*)d_in[14];
    const float* W1   = (const float*)d_in[15]; const float* b1  = (const float*)d_in[16];
    const float* W2   = (const float*)d_in[17]; const float* b2  = (const float*)d_in[18];
    const float* g1   = (const float*)d_in[19]; const float* be1 = (const float*)d_in[20];
    const float* g2   = (const float*)d_in[21]; const float* be2 = (const float*)d_in[22];
    const int*   lidx = (const int*)d_in[23];

    float* out_p   = (float*)d_out;
    float* a_p     = out_p + (size_t)MROWS * Dsz;
    float* attnh_p = a_p + (size_t)Bsz * (Ssz - 1);

    void* base = nullptr;
    cudaGetSymbolAddress(&base, g_scratch);
    float* qn  = (float*)base;
    float* kn  = qn  + (size_t)MROWS * Dsz;
    float* xn  = kn  + (size_t)MROWS * Dsz;
    float* qb  = xn  + (size_t)MROWS * Dsz;
    float* kb  = qb  + (size_t)MROWS * Dsz;
    float* vb  = kb  + (size_t)MROWS * Dsz;
    float* ctx = vb  + (size_t)MROWS * Dsz;
    float* x1  = ctx + (size_t)MROWS * Dsz;
    float* xn2 = x1  + (size_t)MROWS * Dsz;
    float* hid = xn2 + (size_t)MROWS * Dsz;
    float* Lb  = hid + (size_t)MROWS * FFsz;

    cudaFuncSetAttribute(attn_fused_kernel,
                         cudaFuncAttributeMaxDynamicSharedMemorySize, ATT_SMEM_BYTES);
    cudaFuncSetAttribute(gemm_tf32b_kernel,
                         cudaFuncAttributeMaxDynamicSharedMemorySize, GEMM_SMEM_BYTES);

    const dim3 blk(256);

    // affinity projections: qn & kn fused (z=2)
    {
        GemmBatch gbat;
        gbat.a[0] = { x, Wqn, bqn, nullptr, qn };
        gbat.a[1] = { x, Wkn, bkn, nullptr, kn };
        gbat.a[2] = gbat.a[0];
        dim3 grid(Dsz / BN, MROWS / BM, 2);
        gemm_tf32b_kernel<<<grid, blk, GEMM_SMEM_BYTES>>>(gbat, MROWS, Dsz, Dsz, 0);
    }
    mask_detect_kernel<<<1, 32>>>((const unsigned char*)mask);
    mask_norm_kernel<<<16, 256>>>(mask);
    affinity_kernel<<<dim3(Ssz - 1, Bsz), 128>>>(qn, kn, prev, lidx, a_p);
    scan_kernel<<<Bsz, 32>>>(a_p, Lb);

    // attention path
    layernorm_kernel<<<MROWS, 256>>>(x, g1, be1, xn);
    {
        GemmBatch gbat;
        gbat.a[0] = { xn, Wq, bq, nullptr, qb };
        gbat.a[1] = { xn, Wk, bk, nullptr, kb };
        gbat.a[2] = { xn, Wv, bv, nullptr, vb };
        dim3 grid(Dsz / BN, MROWS / BM, 3);
        gemm_tf32b_kernel<<<grid, blk, GEMM_SMEM_BYTES>>>(gbat, MROWS, Dsz, Dsz, 0);
    }
    attn_fused_kernel<<<dim3(Ssz / 32, Bsz * Hsz), 256, ATT_SMEM_BYTES>>>(
        qb, kb, vb, Lb, attnh_p, ctx);

    // output proj + residual
    {
        GemmBatch gbat;
        gbat.a[0] = { ctx, Wo, bo, x, x1 };
        gbat.a[1] = gbat.a[0]; gbat.a[2] = gbat.a[0];
        dim3 grid(Dsz / BN, MROWS / BM, 1);
        gemm_tf32b_kernel<<<grid, blk, GEMM_SMEM_BYTES>>>(gbat, MROWS, Dsz, Dsz, 2);
    }
    layernorm_kernel<<<MROWS, 256>>>(x1, g2, be2, xn2);
    // FFN
    {
        GemmBatch gbat;
        gbat.a[0] = { xn2, W1, b1, nullptr, hid };
        gbat.a[1] = gbat.a[0]; gbat.a[2] = gbat.a[0];
        dim3 grid(FFsz / BN, MROWS / BM, 1);
        gemm_tf32b_kernel<<<grid, blk, GEMM_SMEM_BYTES>>>(gbat, MROWS, FFsz, Dsz, 1);
    }
    {
        GemmBatch gbat;
        gbat.a[0] = { hid, W2, b2, x1, out_p };
        gbat.a[1] = gbat.a[0]; gbat.a[2] = gbat.a[0];
        dim3 grid(Dsz / BN, MROWS / BM, 1);
        gemm_tf32b_kernel<<<grid, blk, GEMM_SMEM_BYTES>>>(gbat, MROWS, Dsz, FFsz, 2);
    }
}

// round 9
// speedup vs baseline: 2.0948x; 1.1438x over previous
#include <cuda_runtime.h>
#include <math.h>
#include <stdint.h>

// Problem constants
#define Bsz 8
#define Ssz 512
#define Dsz 768
#define Hsz 12
#define DHsz 64
#define FFsz 3072
#define MROWS (Bsz*Ssz)   // 4096

// ---------------------------------------------------------------------------
// Scratch (single __device__ global; no allocations anywhere)
#define SCRATCH_FLOATS (9*(size_t)MROWS*Dsz + (size_t)MROWS*FFsz + Bsz*Ssz)
static __device__ float g_scratch[SCRATCH_FLOATS];
static __device__ unsigned char g_mask[Bsz*Ssz];
static __device__ int g_mask_is_int;

// ---------------------------------------------------------------------------
__device__ __forceinline__ void mma_tf32(float* c, const float* a, const float* b) {
    asm volatile(
        "mma.sync.aligned.m16n8k8.row.col.f32.tf32.tf32.f32 "
        "{%0,%1,%2,%3}, {%4,%5,%6,%7}, {%8,%9}, {%0,%1,%2,%3};\n"
        : "+f"(c[0]), "+f"(c[1]), "+f"(c[2]), "+f"(c[3])
        : "r"(__float_as_uint(a[0])), "r"(__float_as_uint(a[1])),
          "r"(__float_as_uint(a[2])), "r"(__float_as_uint(a[3])),
          "r"(__float_as_uint(b[0])), "r"(__float_as_uint(b[1])));
}

__device__ __forceinline__ void cp_async16(uint32_t saddr, const void* gptr) {
    asm volatile("cp.async.cg.shared.global [%0], [%1], 16;\n"
                 :: "r"(saddr), "l"(gptr));
}
__device__ __forceinline__ void cp_commit() {
    asm volatile("cp.async.commit_group;\n");
}
__device__ __forceinline__ void cp_wait0() {
    asm volatile("cp.async.wait_group 0;\n");
}

// ---------------------------------------------------------------------------
// TF32 tensor-core GEMM v3: cp.async staging, natural layouts, no cvt
// (HMMA reads top 19 bits of f32 = tf32 truncation).
// CTA tile 128x128, BK=32, 256 threads (8 warps), warp tile 64x32.
#define BM 128
#define BN 128
#define BK 32
#define A_STR 36
#define B_STR 136
#define A_STAGE_FLT (BM*A_STR)               // 4608
#define B_STAGE_FLT (BK*B_STR)               // 4352
#define STAGE_FLT (A_STAGE_FLT + B_STAGE_FLT) // 8960
#define GEMM_SMEM_BYTES (2*STAGE_FLT*4)       // 71680

struct GemmArgs { const float* X; const float* W; const float* bias; const float* res; float* Y; };
struct GemmBatch { GemmArgs a[3]; };

__global__ __launch_bounds__(256, 2) void gemm_tf32c_kernel(
    GemmBatch gb, int M, int N, int K, int fuse)
{
    const GemmArgs ga = gb.a[blockIdx.z];
    const float* __restrict__ X = ga.X;
    const float* __restrict__ W = ga.W;
    const float* __restrict__ bias = ga.bias;
    const float* __restrict__ res = ga.res;
    float* __restrict__ Y = ga.Y;

    extern __shared__ float dsm[];
    const uint32_t smem_u32 = (uint32_t)__cvta_generic_to_shared(dsm);

    const int tid  = threadIdx.x;
    const int wid  = tid >> 5, lane = tid & 31;
    const int gID  = lane >> 2;        // 0..7
    const int tig  = lane & 3;         // 0..3
    const int warp_m = (wid & 1) * 64;
    const int warp_n = (wid >> 1) * 32;
    const int m0 = blockIdx.y * BM, n0 = blockIdx.x * BN;

    // staging maps (per thread: 4 A chunks + 4 B chunks of 16B)
    const int arow0 = tid >> 3;          // +32*i
    const int akq   = tid & 7;           // 16B chunk within A row
    const int brow0 = tid >> 5;          // +8*i
    const int bcq   = tid & 31;          // 16B chunk within B row

    float acc[4][4][4];
    #pragma unroll
    for (int i = 0; i < 4; i++)
        #pragma unroll
        for (int j = 0; j < 4; j++)
            #pragma unroll
            for (int c = 0; c < 4; c++) acc[i][j][c] = 0.0f;

    const int nk = K / BK;

    // stage tile kt into buffer buf
    auto stage = [&](int kt, int buf) {
        const uint32_t sbase = smem_u32 + (uint32_t)buf * (STAGE_FLT * 4);
        #pragma unroll
        for (int i = 0; i < 4; i++) {
            const int ar = arow0 + 32 * i;
            cp_async16(sbase + (uint32_t)(ar * A_STR + akq * 4) * 4,
                       X + (size_t)(m0 + ar) * K + kt * BK + akq * 4);
        }
        #pragma unroll
        for (int i = 0; i < 4; i++) {
            const int br = brow0 + 8 * i;
            cp_async16(sbase + (uint32_t)(A_STAGE_FLT + br * B_STR + bcq * 4) * 4,
                       W + (size_t)(kt * BK + br) * N + n0 + bcq * 4);
        }
    };

    stage(0, 0);
    cp_commit();

    for (int kt = 0; kt < nk; kt++) {
        const int buf = kt & 1;
        cp_wait0();
        __syncthreads();
        if (kt + 1 < nk) { stage(kt + 1, buf ^ 1); cp_commit(); }

        const float* As = dsm + buf * STAGE_FLT;
        const float* Bs = As + A_STAGE_FLT;
        #pragma unroll
        for (int kkg = 0; kkg < 4; kkg++) {
            const int kk = kkg * 8;
            float af[4][4], bf[4][2];
            #pragma unroll
            for (int mt = 0; mt < 4; mt++) {
                const int m = warp_m + mt * 16 + gID;
                af[mt][0] = As[m * A_STR + kk + tig];
                af[mt][1] = As[(m + 8) * A_STR + kk + tig];
                af[mt][2] = As[m * A_STR + kk + tig + 4];
                af[mt][3] = As[(m + 8) * A_STR + kk + tig + 4];
            }
            #pragma unroll
            for (int nt = 0; nt < 4; nt++) {
                const int n = warp_n + nt * 8 + gID;
                bf[nt][0] = Bs[(kk + tig) * B_STR + n];
                bf[nt][1] = Bs[(kk + tig + 4) * B_STR + n];
            }
            #pragma unroll
            for (int mt = 0; mt < 4; mt++)
                #pragma unroll
                for (int nt = 0; nt < 4; nt++)
                    mma_tf32(acc[mt][nt], af[mt], bf[nt]);
        }
    }

    // epilogue
    #pragma unroll
    for (int mt = 0; mt < 4; mt++) {
        const int m = m0 + warp_m + mt * 16 + gID;
        #pragma unroll
        for (int nt = 0; nt < 4; nt++) {
            const int n = n0 + warp_n + nt * 8 + 2 * tig;
            const float* c = acc[mt][nt];
            const float bv0 = bias[n], bv1 = bias[n + 1];
            float v00 = c[0] + bv0, v01 = c[1] + bv1;
            float v10 = c[2] + bv0, v11 = c[3] + bv1;
            if (fuse == 1) {
                v00 = fmaxf(v00, 0.0f); v01 = fmaxf(v01, 0.0f);
                v10 = fmaxf(v10, 0.0f); v11 = fmaxf(v11, 0.0f);
            } else if (fuse == 2) {
                v00 += res[(size_t)m * N + n];       v01 += res[(size_t)m * N + n + 1];
                v10 += res[(size_t)(m + 8) * N + n]; v11 += res[(size_t)(m + 8) * N + n + 1];
            }
            *(float2*)(Y + (size_t)m * N + n)       = make_float2(v00, v01);
            *(float2*)(Y + (size_t)(m + 8) * N + n) = make_float2(v10, v11);
        }
    }
}

// ---------------------------------------------------------------------------
// LayerNorm over last dim (768), one block per row.
__global__ __launch_bounds__(256) void layernorm_kernel(
    const float* __restrict__ X, const float* __restrict__ g,
    const float* __restrict__ be, float* __restrict__ Y)
{
    __shared__ float red[256];
    __shared__ float s_mean, s_inv;
    const int row = blockIdx.x, tid = threadIdx.x;
    const float* x = X + (size_t)row * Dsz;

    float s = 0.0f;
    for (int i = tid; i < Dsz; i += 256) s += x[i];
    red[tid] = s; __syncthreads();
    for (int o = 128; o > 0; o >>= 1) { if (tid < o) red[tid] += red[tid + o]; __syncthreads(); }
    if (tid == 0) s_mean = red[0] * (1.0f / Dsz);
    __syncthreads();
    const float m = s_mean;

    float v = 0.0f;
    for (int i = tid; i < Dsz; i += 256) { float d = x[i] - m; v += d * d; }
    red[tid] = v; __syncthreads();
    for (int o = 128; o > 0; o >>= 1) { if (tid < o) red[tid] += red[tid + o]; __syncthreads(); }
    if (tid == 0) s_inv = rsqrtf(red[0] * (1.0f / Dsz) + 1e-5f);
    __syncthreads();
    const float inv = s_inv;

    float* y = Y + (size_t)row * Dsz;
    for (int i = tid; i < Dsz; i += 256) y[i] = (x[i] - m) * inv * g[i] + be[i];
}

// ---------------------------------------------------------------------------
// Neighbor affinity
__global__ __launch_bounds__(128) void affinity_kernel(
    const float* __restrict__ qn, const float* __restrict__ kn,
    const float* __restrict__ prev, const int* __restrict__ lidx,
    float* __restrict__ a_out)
{
    const int t = blockIdx.x, b = blockIdx.y, tid = threadIdx.x;
    const float* q0 = qn + ((size_t)b * Ssz + t) * Dsz;
    const float* q1 = q0 + Dsz;
    const float* k0 = kn + ((size_t)b * Ssz + t) * Dsz;
    const float* k1 = k0 + Dsz;
    float sf = 0.0f, sb = 0.0f;
    for (int i = tid; i < Dsz; i += 128) { sf += q0[i] * k1[i]; sb += q1[i] * k0[i]; }
    __shared__ float rf[128], rb[128];
    rf[tid] = sf; rb[tid] = sb; __syncthreads();
    for (int o = 64; o > 0; o >>= 1) {
        if (tid < o) { rf[tid] += rf[tid + o]; rb[tid] += rb[tid + o]; }
        __syncthreads();
    }
    if (tid == 0) {
        float f = rf[0] * (1.0f / 64.0f), bw = rb[0] * (1.0f / 64.0f);
        float ah = 0.5f * (1.0f / (1.0f + expf(-f)) + 1.0f / (1.0f + expf(-bw)));
        float a;
        if (*lidx == 0) a = ah;
        else { float p = prev[(size_t)b * (Ssz - 1) + t]; a = p + (1.0f - p) * ah; }
        a_out[(size_t)b * (Ssz - 1) + t] = a;
    }
}

// L[b,0]=0; L[b,k]=sum_{t<k} log(a[b,t])
__global__ void scan_kernel(const float* __restrict__ a, float* __restrict__ Lout)
{
    const int b = blockIdx.x;
    if (threadIdx.x == 0) {
        float acc = 0.0f;
        Lout[(size_t)b * Ssz] = 0.0f;
        for (int t = 0; t < Ssz - 1; t++) {
            acc += logf(a[(size_t)b * (Ssz - 1) + t]);
            Lout[(size_t)b * Ssz + t + 1] = acc;
        }
    }
}

// ---------------------------------------------------------------------------
// Mask dtype handling (jax bool may land as uint8 or int32)
__global__ void mask_detect_kernel(const unsigned char* __restrict__ m)
{
    if (threadIdx.x == 0)
        g_mask_is_int = (m[1] == 0 && m[2] == 0 && m[3] == 0) ? 1 : 0;
}
__global__ void mask_norm_kernel(const void* __restrict__ m)
{
    int i = blockIdx.x * 256 + threadIdx.x;
    if (i < Bsz * Ssz) {
        int v = g_mask_is_int ? ((const int*)m)[i] : (int)((const unsigned char*)m)[i];
        g_mask[i] = v ? 1 : 0;
    }
}

// ---------------------------------------------------------------------------
// Fused attention (R3 structure; expf -> __expf)
#define ATT_SC 0
#define ATT_QS 16512
#define ATT_KT 18592
#define ATT_LS 26912
#define ATT_MS 27424
#define ATT_SMEM_BYTES ((ATT_MS + 128) * 4)

__global__ __launch_bounds__(256) void attn_fused_kernel(
    const float* __restrict__ gq, const float* __restrict__ gk,
    const float* __restrict__ gv, const float* __restrict__ Lg,
    float* __restrict__ attnh, float* __restrict__ ctx)
{
    extern __shared__ float sm[];
    float* Sc = sm + ATT_SC;
    float* qs = sm + ATT_QS;
    float* kt = sm + ATT_KT;
    float* Ls = sm + ATT_LS;
    unsigned char* ms = (unsigned char*)(sm + ATT_MS);

    const int tid = threadIdx.x;
    const int bh = blockIdx.y, b = bh / Hsz, h = bh % Hsz;
    const int q0 = blockIdx.x * 32;

    for (int i = tid; i < Ssz; i += 256) {
        Ls[i] = Lg[(size_t)b * Ssz + i];
        ms[i] = g_mask[(size_t)b * Ssz + i];
    }
    {
        int r = tid >> 3, d8 = (tid & 7) << 3;
        const float* src = gq + ((size_t)b * Ssz + q0 + r) * Dsz + h * DHsz + d8;
        float* dst = qs + r * 65 + d8;
        #pragma unroll
        for (int u = 0; u < 8; u++) dst[u] = src[u];
    }
    __syncthreads();

    const int qg = tid >> 5;
    const int kg = tid & 31;

    for (int t = 0; t < 4; t++) {
        const int k0 = t * 128;
        {
            int krow = tid >> 1, dd = (tid & 1) << 5;
            const float* src = gk + ((size_t)b * Ssz + k0 + krow) * Dsz + h * DHsz + dd;
            float* dst = kt + krow * 65 + dd;
            #pragma unroll
            for (int u = 0; u < 32; u++) dst[u] = src[u];
        }
        __syncthreads();
        float acc[4][4] = {};
        #pragma unroll 4
        for (int dh = 0; dh < DHsz; dh++) {
            float qv[4], kv[4];
            #pragma unroll
            for (int i = 0; i < 4; i++) qv[i] = qs[(qg * 4 + i) * 65 + dh];
            #pragma unroll
            for (int j = 0; j < 4; j++) kv[j] = kt[(kg + 32 * j) * 65 + dh];
            #pragma unroll
            for (int i = 0; i < 4; i++)
                #pragma unroll
                for (int j = 0; j < 4; j++) acc[i][j] += qv[i] * kv[j];
        }
        #pragma unroll
        for (int i = 0; i < 4; i++)
            #pragma unroll
            for (int j = 0; j < 4; j++) {
                int kgl = k0 + kg + 32 * j;
                float vv = acc[i][j] * 0.125f;
                if (!ms[kgl]) vv = -1e9f;
                Sc[(qg * 4 + i) * 516 + kgl] = vv;
            }
        __syncthreads();
    }

    {
        const int row = tid >> 3, l8 = tid & 7;
        float* sr = Sc + row * 516;
        float mx = -1e30f;
        #pragma unroll 8
        for (int i = 0; i < 64; i++) mx = fmaxf(mx, sr[l8 + 8 * i]);
        for (int o = 1; o < 8; o <<= 1) mx = fmaxf(mx, __shfl_xor_sync(0xffffffffu, mx, o));
        float sum = 0.0f;
        #pragma unroll 8
        for (int i = 0; i < 64; i++) {
            int k = l8 + 8 * i;
            float e = __expf(sr[k] - mx);
            sr[k] = e; sum += e;
        }
        for (int o = 1; o < 8; o <<= 1) sum += __shfl_xor_sync(0xffffffffu, sum, o);
        const float inv = 1.0f / sum;
        const int qi = q0 + row;
        const float Lq = Ls[qi];
        #pragma unroll 8
        for (int i = 0; i < 64; i++) {
            int k = l8 + 8 * i;
            float Lk = Ls[k];
            float c = (qi >= k) ? __expf(Lq - Lk) : __expf(Lk - Lq);
            sr[k] = sr[k] * inv * c;
        }
    }
    __syncthreads();

    {
        float* dst = attnh + (size_t)bh * Ssz * Ssz + (size_t)q0 * Ssz;
        for (int idx = tid; idx < 32 * 512; idx += 256) {
            int r = idx >> 9, k = idx & 511;
            dst[(size_t)r * Ssz + k] = Sc[r * 516 + k];
        }
    }

    float oacc[2][4] = {};
    const int r0 = (tid >> 4) << 1;
    const int c0 = (tid & 15) << 2;
    for (int t = 0; t < 4; t++) {
        const int k0 = t * 128;
        __syncthreads();
        {
            int krow = tid >> 1, dd = (tid & 1) << 5;
            const float* src = gv + ((size_t)b * Ssz + k0 + krow) * Dsz + h * DHsz + dd;
            float* dst = kt + krow * 65 + dd;
            #pragma unroll
            for (int u = 0; u < 32; u++) dst[u] = src[u];
        }
        __syncthreads();
        #pragma unroll 4
        for (int kk = 0; kk < 128; kk++) {
            float a0 = Sc[r0 * 516 + k0 + kk];
            float a1 = Sc[(r0 + 1) * 516 + k0 + kk];
            const float* vr = kt + kk * 65 + c0;
            #pragma unroll
            for (int j = 0; j < 4; j++) { float bv = vr[j]; oacc[0][j] += a0 * bv; oacc[1][j] += a1 * bv; }
        }
    }
    #pragma unroll
    for (int rr = 0; rr < 2; rr++) {
        float4 o4 = make_float4(oacc[rr][0], oacc[rr][1], oacc[rr][2], oacc[rr][3]);
        *(float4*)(ctx + ((size_t)b * Ssz + q0 + r0 + rr) * Dsz + h * DHsz + c0) = o4;
    }
}

// ---------------------------------------------------------------------------
extern "C" void kernel_launch(void* const* d_in, const int* in_sizes, int n_in,
                              void* d_out, int out_size)
{
    (void)in_sizes; (void)n_in; (void)out_size;
    const float* x    = (const float*)d_in[0];
    const void*  mask = d_in[1];
    const float* prev = (const float*)d_in[2];
    const float* Wqn  = (const float*)d_in[3];  const float* bqn = (const float*)d_in[4];
    const float* Wkn  = (const float*)d_in[5];  const float* bkn = (const float*)d_in[6];
    const float* Wq   = (const float*)d_in[7];  const float* bq  = (const float*)d_in[8];
    const float* Wk   = (const float*)d_in[9];  const float* bk  = (const float*)d_in[10];
    const float* Wv   = (const float*)d_in[11]; const float* bv  = (const float*)d_in[12];
    const float* Wo   = (const float*)d_in[13]; const float* bo  = (const float*)d_in[14];
    const float* W1   = (const float*)d_in[15]; const float* b1  = (const float*)d_in[16];
    const float* W2   = (const float*)d_in[17]; const float* b2  = (const float*)d_in[18];
    const float* g1   = (const float*)d_in[19]; const float* be1 = (const float*)d_in[20];
    const float* g2   = (const float*)d_in[21]; const float* be2 = (const float*)d_in[22];
    const int*   lidx = (const int*)d_in[23];

    float* out_p   = (float*)d_out;
    float* a_p     = out_p + (size_t)MROWS * Dsz;
    float* attnh_p = a_p + (size_t)Bsz * (Ssz - 1);

    void* base = nullptr;
    cudaGetSymbolAddress(&base, g_scratch);
    float* qn  = (float*)base;
    float* kn  = qn  + (size_t)MROWS * Dsz;
    float* xn  = kn  + (size_t)MROWS * Dsz;
    float* qb  = xn  + (size_t)MROWS * Dsz;
    float* kb  = qb  + (size_t)MROWS * Dsz;
    float* vb  = kb  + (size_t)MROWS * Dsz;
    float* ctx = vb  + (size_t)MROWS * Dsz;
    float* x1  = ctx + (size_t)MROWS * Dsz;
    float* xn2 = x1  + (size_t)MROWS * Dsz;
    float* hid = xn2 + (size_t)MROWS * Dsz;
    float* Lb  = hid + (size_t)MROWS * FFsz;

    cudaFuncSetAttribute(attn_fused_kernel,
                         cudaFuncAttributeMaxDynamicSharedMemorySize, ATT_SMEM_BYTES);
    cudaFuncSetAttribute(gemm_tf32c_kernel,
                         cudaFuncAttributeMaxDynamicSharedMemorySize, GEMM_SMEM_BYTES);

    const dim3 blk(256);

    // affinity projections: qn & kn fused (z=2)
    {
        GemmBatch gbat;
        gbat.a[0] = { x, Wqn, bqn, nullptr, qn };
        gbat.a[1] = { x, Wkn, bkn, nullptr, kn };
        gbat.a[2] = gbat.a[0];
        dim3 grid(Dsz / BN, MROWS / BM, 2);
        gemm_tf32c_kernel<<<grid, blk, GEMM_SMEM_BYTES>>>(gbat, MROWS, Dsz, Dsz, 0);
    }
    mask_detect_kernel<<<1, 32>>>((const unsigned char*)mask);
    mask_norm_kernel<<<16, 256>>>(mask);
    affinity_kernel<<<dim3(Ssz - 1, Bsz), 128>>>(qn, kn, prev, lidx, a_p);
    scan_kernel<<<Bsz, 32>>>(a_p, Lb);

    // attention path
    layernorm_kernel<<<MROWS, 256>>>(x, g1, be1, xn);
    {
        GemmBatch gbat;
        gbat.a[0] = { xn, Wq, bq, nullptr, qb };
        gbat.a[1] = { xn, Wk, bk, nullptr, kb };
        gbat.a[2] = { xn, Wv, bv, nullptr, vb };
        dim3 grid(Dsz / BN, MROWS / BM, 3);
        gemm_tf32c_kernel<<<grid, blk, GEMM_SMEM_BYTES>>>(gbat, MROWS, Dsz, Dsz, 0);
    }
    attn_fused_kernel<<<dim3(Ssz / 32, Bsz * Hsz), 256, ATT_SMEM_BYTES>>>(
        qb, kb, vb, Lb, attnh_p, ctx);

    // output proj + residual
    {
        GemmBatch gbat;
        gbat.a[0] = { ctx, Wo, bo, x, x1 };
        gbat.a[1] = gbat.a[0]; gbat.a[2] = gbat.a[0];
        dim3 grid(Dsz / BN, MROWS / BM, 1);
        gemm_tf32c_kernel<<<grid, blk, GEMM_SMEM_BYTES>>>(gbat, MROWS, Dsz, Dsz, 2);
    }
    layernorm_kernel<<<MROWS, 256>>>(x1, g2, be2, xn2);
    // FFN
    {
        GemmBatch gbat;
        gbat.a[0] = { xn2, W1, b1, nullptr, hid };
        gbat.a[1] = gbat.a[0]; gbat.a[2] = gbat.a[0];
        dim3 grid(FFsz / BN, MROWS / BM, 1);
        gemm_tf32c_kernel<<<grid, blk, GEMM_SMEM_BYTES>>>(gbat, MROWS, FFsz, Dsz, 1);
    }
    {
        GemmBatch gbat;
        gbat.a[0] = { hid, W2, b2, x1, out_p };
        gbat.a[1] = gbat.a[0]; gbat.a[2] = gbat.a[0];
        dim3 grid(Dsz / BN, MROWS / BM, 1);
        gemm_tf32c_kernel<<<grid, blk, GEMM_SMEM_BYTES>>>(gbat, MROWS, Dsz, FFsz, 2);
    }
}